// round 7
// baseline (speedup 1.0000x reference)
#include <cuda_runtime.h>
#include <cstdint>

#define NN 50000
#define NE 800000
#define SD 128
#define NG 128
#define NC 41
#define BN_EPS 1e-5f

typedef unsigned int u32;
typedef unsigned short u16;

// ---------------- scratch (static device globals; no runtime alloc) -------
__device__ u32   g_xa[NN * SD];       // packed (bf16hi | bf16lo<<16) per element
__device__ u32   g_xb[NN * SD];       // double buffer
__device__ int   g_deg[NN];
__device__ int   g_rowptr[NN + 1];
__device__ int   g_cursor[NN];
__device__ int   g_csrsrc[NE];
__device__ int   g_bsum[64];
__device__ float g_pool[NG * SD];

// combined bf16 hi/lo W fragments: uint4 per (ks,nt,lane) = (h0,h1,l0,l1)
#define WFU4 4096                       // fragments per matrix
__device__ __align__(16) uint4 g_wf[4 * WFU4];

// ---------------- bf16 split helpers --------------------------------------
__device__ __forceinline__ u32 f2bf(float f) {          // RN-even, returns 16-bit
    u32 u = __float_as_uint(f);
    return (u + 0x7fffu + ((u >> 16) & 1u)) >> 16;
}
__device__ __forceinline__ u32 packsplit(float v) {
    u32 h = f2bf(v);
    float hv = __uint_as_float(h << 16);
    u32 l = f2bf(v - hv);
    return h | (l << 16);
}
__device__ __forceinline__ float unpack(u32 p) {
    return __uint_as_float(p << 16) + __uint_as_float(p & 0xffff0000u);
}
__device__ __forceinline__ u32 prmt(u32 a, u32 b, u32 s) {
    u32 d; asm("prmt.b32 %0,%1,%2,%3;" : "=r"(d) : "r"(a), "r"(b), "r"(s)); return d;
}

__device__ __forceinline__ void mma16816(float* c, const u32* a, const u32* b) {
    asm volatile(
        "mma.sync.aligned.m16n8k16.row.col.f32.bf16.bf16.f32 "
        "{%0,%1,%2,%3}, {%4,%5,%6,%7}, {%8,%9}, {%0,%1,%2,%3};"
        : "+f"(c[0]), "+f"(c[1]), "+f"(c[2]), "+f"(c[3])
        : "r"(a[0]), "r"(a[1]), "r"(a[2]), "r"(a[3]), "r"(b[0]), "r"(b[1]));
}

// ---------------- CSR build kernels ----------------------------------------
__global__ void k_zero_deg() {
    int i = blockIdx.x * blockDim.x + threadIdx.x;
    if (i < NN) g_deg[i] = 0;
}
__global__ void k_hist(const int* __restrict__ dst) {
    int e = blockIdx.x * blockDim.x + threadIdx.x;
    if (e < NE) atomicAdd(&g_deg[dst[e]], 1);
}
// 3-phase scan: block-local exclusive scans + block sums, tiny scan, fixup
__global__ void k_scan1() {
    __shared__ int ws[32];
    int tid = threadIdx.x, lane = tid & 31, wid = tid >> 5;
    int i = blockIdx.x * 1024 + tid;
    int v = (i < NN) ? g_deg[i] : 0;
    int s = v;
#pragma unroll
    for (int d = 1; d < 32; d <<= 1) {
        int t = __shfl_up_sync(0xffffffffu, s, d);
        if (lane >= d) s += t;
    }
    if (lane == 31) ws[wid] = s;
    __syncthreads();
    if (wid == 0) {
        int t = ws[lane];
#pragma unroll
        for (int d = 1; d < 32; d <<= 1) {
            int u = __shfl_up_sync(0xffffffffu, t, d);
            if (lane >= d) t += u;
        }
        ws[lane] = t;
    }
    __syncthreads();
    int excl = (wid ? ws[wid - 1] : 0) + s - v;
    if (i < NN) g_rowptr[i] = excl;
    if (tid == 1023) g_bsum[blockIdx.x] = excl + v;
}
__global__ void k_scan2() {   // 64 threads, scans 49 block sums (exclusive)
    int t = threadIdx.x;
    int v = (t < 49) ? g_bsum[t] : 0;
    int s = v;
#pragma unroll
    for (int d = 1; d < 32; d <<= 1) {
        int u = __shfl_up_sync(0xffffffffu, s, d);
        if ((t & 31) >= d) s += u;
    }
    __shared__ int w0;
    if (t == 31) w0 = s;
    __syncthreads();
    if (t >= 32) s += w0;
    if (t < 49) g_bsum[t] = s - v;
    if (t == 48) g_rowptr[NN] = s;
}
__global__ void k_scan3() {
    int i = blockIdx.x * 1024 + threadIdx.x;
    if (i < NN) {
        int r = g_rowptr[i] + g_bsum[blockIdx.x];
        g_rowptr[i] = r;
        g_cursor[i] = r;
    }
}
__global__ void k_csr(const int* __restrict__ src, const int* __restrict__ dst) {
    int e = blockIdx.x * blockDim.x + threadIdx.x;
    if (e < NE) {
        int p = atomicAdd(&g_cursor[dst[e]], 1);
        g_csrsrc[p] = src[e];
    }
}

// ---------------- W split: all 4 matrices in one launch --------------------
__global__ void k_wsplit4(const float* __restrict__ W0, const float* __restrict__ W1,
                          const float* __restrict__ W2, const float* __restrict__ W3) {
    int t = blockIdx.x * blockDim.x + threadIdx.x;
    if (t >= 4 * 128 * 128) return;
    int m = t >> 14, r = t & 16383;
    int n = r >> 7, k = r & 127;
    const float* W = (m == 0) ? W0 : (m == 1) ? W1 : (m == 2) ? W2 : W3;
    float v = W[n * 128 + k];
    u32 h = f2bf(v);
    u32 l = f2bf(v - __uint_as_float(h << 16));
    int ks = k >> 4, nt = n >> 3, kl = k & 15;
    int lane = ((n & 7) << 2) | ((kl >> 1) & 3);
    int f = (ks * 16 + nt) * 32 + lane;
    int reg = kl >> 3, half = kl & 1;
    u16* base = (u16*)(g_wf + (long)m * WFU4 + f);
    base[reg * 2 + half]     = (u16)h;     // hi limbs in .x/.y
    base[4 + reg * 2 + half] = (u16)l;     // lo limbs in .z/.w
}

// ---------------- fused layer kernel ---------------------------------------
__device__ __forceinline__ void gemm_pass(
    const u32* sA, const uint4* wf, int wm, int wn, int lane, float acc[2][8][4])
{
#pragma unroll
    for (int m = 0; m < 2; m++)
#pragma unroll
        for (int n = 0; n < 8; n++)
#pragma unroll
            for (int j = 0; j < 4; j++) acc[m][n][j] = 0.f;

#pragma unroll
    for (int ks = 0; ks < 8; ks++) {
        u32 ah[2][4], al[2][4];
#pragma unroll
        for (int m = 0; m < 2; m++) {
            int row0 = wm + m * 16 + (lane >> 2);
            int row1 = row0 + 8;
            int kp0 = ks * 8 + (lane & 3);
            int kp1 = kp0 + 4;
            int g00 = row0 * 64 + (kp0 ^ ((row0 & 7) << 2));
            int g10 = row1 * 64 + (kp0 ^ ((row1 & 7) << 2));
            int g01 = row0 * 64 + (kp1 ^ ((row0 & 7) << 2));
            int g11 = row1 * 64 + (kp1 ^ ((row1 & 7) << 2));
            uint2 p00 = *(const uint2*)(sA + g00 * 2);
            uint2 p10 = *(const uint2*)(sA + g10 * 2);
            uint2 p01 = *(const uint2*)(sA + g01 * 2);
            uint2 p11 = *(const uint2*)(sA + g11 * 2);
            ah[m][0] = prmt(p00.x, p00.y, 0x5410); al[m][0] = prmt(p00.x, p00.y, 0x7632);
            ah[m][1] = prmt(p10.x, p10.y, 0x5410); al[m][1] = prmt(p10.x, p10.y, 0x7632);
            ah[m][2] = prmt(p01.x, p01.y, 0x5410); al[m][2] = prmt(p01.x, p01.y, 0x7632);
            ah[m][3] = prmt(p11.x, p11.y, 0x5410); al[m][3] = prmt(p11.x, p11.y, 0x7632);
        }
#pragma unroll
        for (int n = 0; n < 8; n++) {
            int nt = (wn >> 3) + n;
            uint4 w = __ldg(wf + (ks * 16 + nt) * 32 + lane);
            const u32* bh = (const u32*)&w;      // w.x, w.y
            const u32* bl = bh + 2;              // w.z, w.w
#pragma unroll
            for (int m = 0; m < 2; m++) {
                mma16816(acc[m][n], ah[m], bh);
                mma16816(acc[m][n], ah[m], bl);
                mma16816(acc[m][n], al[m], bh);
            }
        }
    }
}

template <int BN_MODE, int EMBED>
__global__ void __launch_bounds__(256, 2) k_layer(
    const u32* __restrict__ X, const float* __restrict__ emb,
    const int* __restrict__ ids, u32* __restrict__ Xout,
    const uint4* __restrict__ wf1, const float* __restrict__ b1,
    const uint4* __restrict__ wf2, const float* __restrict__ b2,
    const float* __restrict__ gamma, const float* __restrict__ beta,
    const float* __restrict__ mean, const float* __restrict__ var)
{
    extern __shared__ __align__(16) u32 sA[];   // 128 * 64 * 2 u32 = 64KB
    const int tid  = threadIdx.x;
    const int lane = tid & 31;
    const int wid  = tid >> 5;
    const int r0   = blockIdx.x * 128;
    const int wm   = (wid & 3) * 32;
    const int wn   = (wid >> 2) * 64;

    const uint4*  x4 = (const uint4*)X;
    const float4* e4 = (const float4*)emb;

    auto ldrow = [&](int j) -> float4 {
        if (EMBED) {
            return __ldg(e4 + (long)__ldg(ids + j) * 32 + lane);
        } else {
            uint4 v = __ldg(x4 + (long)j * 32 + lane);
            return make_float4(unpack(v.x), unpack(v.y), unpack(v.z), unpack(v.w));
        }
    };

    // ---- Phase A: aggregation y = x_self + sum_neigh, into SMEM ----
#pragma unroll 1
    for (int t = 0; t < 16; t++) {
        int nd = r0 + wid * 16 + t;
        if (nd >= NN) break;
        float4 sv = ldrow(nd);
        float s0 = sv.x, s1 = sv.y, s2 = sv.z, s3 = sv.w;
        int e = g_rowptr[nd], end = g_rowptr[nd + 1];
        for (; e + 4 <= end; e += 4) {
            int j0 = g_csrsrc[e], j1 = g_csrsrc[e + 1];
            int j2 = g_csrsrc[e + 2], j3 = g_csrsrc[e + 3];
            float4 a = ldrow(j0), b = ldrow(j1), c = ldrow(j2), d = ldrow(j3);
            s0 += (a.x + b.x) + (c.x + d.x);
            s1 += (a.y + b.y) + (c.y + d.y);
            s2 += (a.z + b.z) + (c.z + d.z);
            s3 += (a.w + b.w) + (c.w + d.w);
        }
        for (; e < end; e++) {
            float4 a = ldrow(g_csrsrc[e]);
            s0 += a.x; s1 += a.y; s2 += a.z; s3 += a.w;
        }
        int row = nd - r0;
        int g = row * 64 + ((lane * 2) ^ ((row & 7) << 2));
        uint4 o;
        o.x = packsplit(s0); o.y = packsplit(s1);
        o.z = packsplit(s2); o.w = packsplit(s3);
        *(uint4*)(sA + g * 2) = o;
    }
    __syncthreads();

    // ---- Phase B: h = relu(y@W1 + b1), re-split into SMEM ----
    float acc[2][8][4];
    gemm_pass(sA, wf1, wm, wn, lane, acc);
    __syncthreads();
#pragma unroll
    for (int m = 0; m < 2; m++) {
        int row0 = wm + m * 16 + (lane >> 2);
        int row1 = row0 + 8;
#pragma unroll
        for (int n = 0; n < 8; n++) {
            int col = wn + n * 8 + (lane & 3) * 2;
            float bb0 = __ldg(&b1[col]), bb1 = __ldg(&b1[col + 1]);
            float v0 = fmaxf(acc[m][n][0] + bb0, 0.f);
            float v1 = fmaxf(acc[m][n][1] + bb1, 0.f);
            float v2 = fmaxf(acc[m][n][2] + bb0, 0.f);
            float v3 = fmaxf(acc[m][n][3] + bb1, 0.f);
            int kp = col >> 1;
            int g0 = row0 * 64 + (kp ^ ((row0 & 7) << 2));
            int g1 = row1 * 64 + (kp ^ ((row1 & 7) << 2));
            *(uint2*)(sA + g0 * 2) = make_uint2(packsplit(v0), packsplit(v1));
            *(uint2*)(sA + g1 * 2) = make_uint2(packsplit(v2), packsplit(v3));
        }
    }
    __syncthreads();

    // ---- Phase C: x = [bn](relu(h@W2 + b2)) -> global packed ----
    gemm_pass(sA, wf2, wm, wn, lane, acc);
#pragma unroll
    for (int m = 0; m < 2; m++) {
        int row0 = wm + m * 16 + (lane >> 2);
#pragma unroll
        for (int n = 0; n < 8; n++) {
            int col = wn + n * 8 + (lane & 3) * 2;
            float bb0 = __ldg(&b2[col]), bb1 = __ldg(&b2[col + 1]);
            float sc0 = 0.f, sc1 = 0.f, mn0 = 0.f, mn1 = 0.f, bt0 = 0.f, bt1 = 0.f;
            if (BN_MODE) {
                sc0 = __ldg(&gamma[col]) * rsqrtf(__ldg(&var[col]) + BN_EPS);
                sc1 = __ldg(&gamma[col + 1]) * rsqrtf(__ldg(&var[col + 1]) + BN_EPS);
                mn0 = __ldg(&mean[col]); mn1 = __ldg(&mean[col + 1]);
                bt0 = __ldg(&beta[col]); bt1 = __ldg(&beta[col + 1]);
            }
#pragma unroll
            for (int h = 0; h < 2; h++) {
                int r = r0 + row0 + h * 8;
                if (r < NN) {
                    float z0 = fmaxf(acc[m][n][h * 2 + 0] + bb0, 0.f);
                    float z1 = fmaxf(acc[m][n][h * 2 + 1] + bb1, 0.f);
                    if (BN_MODE) {
                        z0 = (z0 - mn0) * sc0 + bt0;
                        z1 = (z1 - mn1) * sc1 + bt1;
                    }
                    *(uint2*)(Xout + (long)r * 128 + col) =
                        make_uint2(packsplit(z0), packsplit(z1));
                }
            }
        }
    }
}

// ---------------- pooling (batch sorted -> run-length accumulate) ----------
__global__ void k_zero_pool() {
    int i = blockIdx.x * blockDim.x + threadIdx.x;
    if (i < NG * SD) g_pool[i] = 0.f;
}
#define NODES_PB 250
__global__ void k_pool(const u32* __restrict__ X, const int* __restrict__ batch) {
    int c = threadIdx.x;
    int n0 = blockIdx.x * NODES_PB;
    int n1 = n0 + NODES_PB;
    if (n1 > NN) n1 = NN;
    if (n0 >= NN) return;
    float acc = 0.f;
    int cur = batch[n0];
    for (int n = n0; n < n1; n++) {
        int b = __ldg(&batch[n]);
        float v = unpack(X[(long)n * SD + c]);
        if (b != cur) {
            atomicAdd(&g_pool[cur * SD + c], acc);
            acc = 0.f; cur = b;
        }
        acc += v;
    }
    atomicAdd(&g_pool[cur * SD + c], acc);
}

// ---------------- tiny FC head: one block per graph -----------------------
__global__ void k_fc(const float* __restrict__ fc1W, const float* __restrict__ fc1b,
                     const float* __restrict__ fc2W, const float* __restrict__ fc2b,
                     float* __restrict__ out) {
    __shared__ float p[SD];
    __shared__ float h[SD];
    int g = blockIdx.x, t = threadIdx.x;
    p[t] = g_pool[g * SD + t];
    __syncthreads();
    float s = fc1b[t];
#pragma unroll 8
    for (int k = 0; k < SD; k++) s += p[k] * fc1W[t * SD + k];
    h[t] = fmaxf(s, 0.f);
    __syncthreads();
    if (t < NC) {
        float s2 = fc2b[t];
#pragma unroll 8
        for (int k = 0; k < SD; k++) s2 += h[k] * fc2W[t * SD + k];
        out[g * NC + t] = s2;
    }
}

// ---------------- launch ---------------------------------------------------
#define SM_LAYER (128 * 64 * 8)

extern "C" void kernel_launch(void* const* d_in, const int* in_sizes, int n_in,
                              void* d_out, int out_size) {
    const int*   node_ids = (const int*)d_in[0];
    const int*   edge     = (const int*)d_in[1];
    const int*   batch    = (const int*)d_in[2];
    const float* emb      = (const float*)d_in[3];
    const float* in_W1    = (const float*)d_in[4];
    const float* in_b1    = (const float*)d_in[5];
    const float* in_W2    = (const float*)d_in[6];
    const float* in_b2    = (const float*)d_in[7];
    const float* bn_gamma = (const float*)d_in[8];
    const float* bn_beta  = (const float*)d_in[9];
    const float* bn_mean  = (const float*)d_in[10];
    const float* bn_var   = (const float*)d_in[11];
    const float* out_W1   = (const float*)d_in[12];
    const float* out_b1   = (const float*)d_in[13];
    const float* out_W2   = (const float*)d_in[14];
    const float* out_b2   = (const float*)d_in[15];
    const float* fc1_W    = (const float*)d_in[16];
    const float* fc1_b    = (const float*)d_in[17];
    const float* fc2_W    = (const float*)d_in[18];
    const float* fc2_b    = (const float*)d_in[19];
    float* out = (float*)d_out;

    const int* src = edge;
    const int* dst = edge + NE;

    u32 *p_xa, *p_xb;
    uint4* p_wf;
    cudaGetSymbolAddress((void**)&p_xa, g_xa);
    cudaGetSymbolAddress((void**)&p_xb, g_xb);
    cudaGetSymbolAddress((void**)&p_wf, g_wf);

    cudaFuncSetAttribute(k_layer<0,0>, cudaFuncAttributeMaxDynamicSharedMemorySize, SM_LAYER);
    cudaFuncSetAttribute(k_layer<1,0>, cudaFuncAttributeMaxDynamicSharedMemorySize, SM_LAYER);
    cudaFuncSetAttribute(k_layer<1,1>, cudaFuncAttributeMaxDynamicSharedMemorySize, SM_LAYER);

    // CSR build
    k_zero_deg<<<(NN + 255) / 256, 256>>>();
    k_hist<<<(NE + 255) / 256, 256>>>(dst);
    k_scan1<<<49, 1024>>>();
    k_scan2<<<1, 64>>>();
    k_scan3<<<49, 1024>>>();
    k_csr<<<(NE + 255) / 256, 256>>>(src, dst);

    // W fragments (all 4 matrices, one launch)
    k_wsplit4<<<256, 256>>>(in_W1, in_W2, out_W1, out_W2);

    const int GB = (NN + 127) / 128;  // 391 blocks

    // layer 1: gathers straight from emb via node_ids
    k_layer<1,1><<<GB, 256, SM_LAYER>>>(nullptr, emb, node_ids, p_xb,
        p_wf, in_b1, p_wf + WFU4, in_b2, bn_gamma, bn_beta, bn_mean, bn_var);

    u32* cur = p_xb;
    u32* nxt = p_xa;
    for (int L = 1; L < 6; L++) {
        if (L < 5)
            k_layer<1,0><<<GB, 256, SM_LAYER>>>(cur, nullptr, nullptr, nxt,
                p_wf, in_b1, p_wf + WFU4, in_b2,
                bn_gamma, bn_beta, bn_mean, bn_var);
        else
            k_layer<0,0><<<GB, 256, SM_LAYER>>>(cur, nullptr, nullptr, nxt,
                p_wf + 2 * WFU4, out_b1, p_wf + 3 * WFU4, out_b2,
                nullptr, nullptr, nullptr, nullptr);
        u32* t = cur; cur = nxt; nxt = t;
    }
    // after 6 layers result is in `cur`

    // pooling + FC head
    k_zero_pool<<<(NG * SD + 255) / 256, 256>>>();
    k_pool<<<(NN + NODES_PB - 1) / NODES_PB, 128>>>(cur, batch);
    k_fc<<<NG, 128>>>(fc1_W, fc1_b, fc2_W, fc2_b, out);
}